// round 6
// baseline (speedup 1.0000x reference)
#include <cuda_runtime.h>
#include <cuda_fp16.h>
#include <cstdint>

#define N_PTS 131072
#define DIM   64
#define KCENT 1024
#define TH_GAP 0.35f

#define ROWS_BLK 128
#define ASSIGN_BLOCKS (N_PTS / ROWS_BLK)   // 1024
#define NCH 128
#define CHUNKS (KCENT / NCH)               // 8

// ---------------- device scratch (no allocation allowed) --------------------
__device__ float g_csq[KCENT];
__device__ int   g_ind[N_PTS];
__device__ int   g_counts[KCENT];
__device__ float g_csum[KCENT * DIM];
__device__ float g_cnew[KCENT * DIM];
__device__ float g_loss;
__device__ float g_sum_cs;
__device__ int   g_nflag;
__device__ int   g_flag[N_PTS];
__device__ float g_Ct[KCENT * DIM];                        // C^T for recheck
__device__ __align__(16) __half2 gXh[ASSIGN_BLOCKS * 64 * 64];  // 16.8 MB: [blk][d][r2]
__device__ __align__(16) __half2 gBh[CHUNKS * 64 * 64];         // 128 KB:  [cc][d][c2]

__device__ __forceinline__ __half2 u2h(uint32_t u) {
    return *reinterpret_cast<__half2*>(&u);
}

// ---------------- small kernels -----------------------------------------------
__global__ void zero_kernel() {
    int i = blockIdx.x * blockDim.x + threadIdx.x;
    if (i < KCENT * DIM) g_csum[i] = 0.0f;
    if (i < KCENT)       g_counts[i] = 0;
    if (i == 0)          { g_loss = 0.0f; g_nflag = 0; }
}

__global__ void csq_kernel(const float* __restrict__ C) {
    int k = blockIdx.x * blockDim.x + threadIdx.x;
    if (k < KCENT) {
        float s = 0.0f;
        #pragma unroll
        for (int d = 0; d < DIM; d++) {
            float c = C[d * KCENT + k];
            s = fmaf(c, c, s);
        }
        g_csq[k] = s;
    }
}

__global__ void sumcs_kernel(const float* __restrict__ cluster_size) {
    __shared__ float red[1024];
    int k = threadIdx.x;
    red[k] = cluster_size[k];
    __syncthreads();
    #pragma unroll
    for (int s = 512; s > 0; s >>= 1) {
        if (k < s) red[k] += red[k + s];
        __syncthreads();
    }
    if (k == 0) g_sum_cs = red[0];
}

// transpose C [64][1024] -> Ct [1024][64] (for exact recheck)
__global__ void prep_Ct(const float* __restrict__ C) {
    __shared__ float t[32][33];
    int tx = threadIdx.x & 31;
    int ty0 = threadIdx.x >> 5;
    int kb = blockIdx.x * 32;
    int db = blockIdx.y * 32;
    #pragma unroll
    for (int yy = 0; yy < 4; yy++) {
        int ty = ty0 + yy * 8;
        t[ty][tx] = C[(db + ty) * KCENT + kb + tx];
    }
    __syncthreads();
    #pragma unroll
    for (int yy = 0; yy < 4; yy++) {
        int ty = ty0 + yy * 8;
        g_Ct[(kb + ty) * DIM + db + tx] = t[tx][ty];
    }
}

// X -> half2 image [blk][d][r2]: pair (row 2*r2, row 2*r2+1) at dim d
__global__ void prep_Xh(const float* __restrict__ X) {
    __shared__ float xs[64 * 132];
    const int tid = threadIdx.x;
    const int b = blockIdx.x;
    const float4* Xv = reinterpret_cast<const float4*>(X + (size_t)b * ROWS_BLK * DIM);
    #pragma unroll
    for (int j = 0; j < 8; j++) {
        int f = tid + j * 256;          // f < 2048
        float4 v = Xv[f];
        int r = f >> 4;
        int d = (f & 15) * 4;
        xs[(d + 0) * 132 + r] = v.x;
        xs[(d + 1) * 132 + r] = v.y;
        xs[(d + 2) * 132 + r] = v.z;
        xs[(d + 3) * 132 + r] = v.w;
    }
    __syncthreads();
    #pragma unroll
    for (int j = 0; j < 16; j++) {
        int f = tid + j * 256;          // f < 4096
        int d = f >> 6, r2 = f & 63;
        gXh[(size_t)b * 4096 + f] =
            __floats2half2_rn(xs[d * 132 + 2 * r2], xs[d * 132 + 2 * r2 + 1]);
    }
}

// C -> half2 image [cc][d][c2]: pair (col cc*128+2*c2, +1) at dim d
__global__ void prep_Bh(const float* __restrict__ C) {
    int i = blockIdx.x * blockDim.x + threadIdx.x;
    if (i >= CHUNKS * 64 * 64) return;
    int cc = i >> 12, d = (i >> 6) & 63, c2 = i & 63;
    int col = cc * NCH + 2 * c2;
    gBh[i] = __floats2half2_rn(C[d * KCENT + col], C[d * KCENT + col + 1]);
}

// ---------------- assign: HFMA2 GEMM + top-2 argmax + fused segsum -----------
__global__ void __launch_bounds__(256, 2)
assign_kernel(const float* __restrict__ X) {
    __shared__ __align__(16) __half2 xh[64 * 68];
    __shared__ __align__(16) __half2 ch[64 * 68];
    __shared__ float s_csq[KCENT];
    __shared__ int   s_ind[ROWS_BLK];
    __shared__ int   s_flg[ROWS_BLK];

    const int tid  = threadIdx.x;
    const int w    = tid >> 5;
    const int lane = tid & 31;
    const int tx   = tid & 15;
    const int ty   = tid >> 4;
    const int rb   = blockIdx.x * ROWS_BLK;

    // load X half2 image (pad stride 68)
    const uint2* srcx = reinterpret_cast<const uint2*>(gXh + (size_t)blockIdx.x * 4096);
    #pragma unroll
    for (int j = 0; j < 8; j++) {
        int f = tid + j * 256;          // f < 2048 (uint2 units)
        int d = f >> 5, r2 = (f & 31) << 1;
        *reinterpret_cast<uint2*>(&xh[d * 68 + r2]) = srcx[f];
    }
    #pragma unroll
    for (int j = 0; j < 4; j++) s_csq[tid + j * 256] = g_csq[tid + j * 256];

    float v1[8], v2[8];
    int   i1[8];
    #pragma unroll
    for (int s = 0; s < 8; s++) { v1[s] = -3.402823466e38f; v2[s] = -3.402823466e38f; i1[s] = 0; }

    const __half2 hzero = __float2half2_rn(0.0f);

    for (int cc = 0; cc < CHUNKS; cc++) {
        __syncthreads();
        const uint2* srcb = reinterpret_cast<const uint2*>(gBh + cc * 4096);
        #pragma unroll
        for (int j = 0; j < 8; j++) {
            int f = tid + j * 256;
            int d = f >> 5, c2 = (f & 31) << 1;
            *reinterpret_cast<uint2*>(&ch[d * 68 + c2]) = srcb[f];
        }
        __syncthreads();

        __half2 acc[8][4];
        #pragma unroll
        for (int i = 0; i < 8; i++)
            #pragma unroll
            for (int jj = 0; jj < 4; jj++) acc[i][jj] = hzero;

        const __half2* xp = &xh[2 * ty];
        const __half2* cp = &ch[2 * tx];
        #pragma unroll 8
        for (int d = 0; d < 64; d++) {
            uint2 au  = *reinterpret_cast<const uint2*>(xp + d * 68);
            uint2 au2 = *reinterpret_cast<const uint2*>(xp + d * 68 + 32);
            uint2 bu  = *reinterpret_cast<const uint2*>(cp + d * 68);
            uint2 bu2 = *reinterpret_cast<const uint2*>(cp + d * 68 + 32);
            __half2 b0 = u2h(bu.x), b1 = u2h(bu.y), b2 = u2h(bu2.x), b3 = u2h(bu2.y);
            __half2 ap[4] = {u2h(au.x), u2h(au.y), u2h(au2.x), u2h(au2.y)};
            #pragma unroll
            for (int g = 0; g < 4; g++) {
                __half2 alo = __half2half2(__low2half(ap[g]));
                __half2 ahi = __half2half2(__high2half(ap[g]));
                int i0 = g * 2, i1r = g * 2 + 1;
                acc[i0][0]  = __hfma2(alo, b0, acc[i0][0]);
                acc[i0][1]  = __hfma2(alo, b1, acc[i0][1]);
                acc[i0][2]  = __hfma2(alo, b2, acc[i0][2]);
                acc[i0][3]  = __hfma2(alo, b3, acc[i0][3]);
                acc[i1r][0] = __hfma2(ahi, b0, acc[i1r][0]);
                acc[i1r][1] = __hfma2(ahi, b1, acc[i1r][1]);
                acc[i1r][2] = __hfma2(ahi, b2, acc[i1r][2]);
                acc[i1r][3] = __hfma2(ahi, b3, acc[i1r][3]);
            }
        }

        // epilogue: scores + running top-2 (cols ascend per thread)
        #pragma unroll
        for (int jj = 0; jj < 4; jj++) {
            int c0 = cc * NCH + ((jj < 2) ? (4 * tx + 2 * jj) : (64 + 4 * tx + 2 * (jj - 2)));
            float cq0 = s_csq[c0], cq1 = s_csq[c0 + 1];
            #pragma unroll
            for (int i = 0; i < 8; i++) {
                float2 f = __half22float2(acc[i][jj]);
                float s0 = fmaf(2.0f, f.x, -cq0);
                float s1 = fmaf(2.0f, f.y, -cq1);
                if (s0 > v1[i]) { v2[i] = v1[i]; v1[i] = s0; i1[i] = c0; }
                else if (s0 > v2[i]) v2[i] = s0;
                if (s1 > v1[i]) { v2[i] = v1[i]; v1[i] = s1; i1[i] = c0 + 1; }
                else if (s1 > v2[i]) v2[i] = s1;
            }
        }
    }

    // reduce top-2 across the 16 tx-lanes sharing each row group
    // rows for this thread: (g<4) ? 4*ty+g : 64+4*ty+(g-4)  mapped via acc rows:
    // acc row i: i = g*2 + h where rows = 2*r2 .. : actual row for acc index i:
    //   g = i>>1 in {0,1}: rows 4ty + (i)            (from au: rows 4ty..4ty+3)
    //   g in {2,3}:        rows 64 + 4ty + (i-4)     (from au2)
    #pragma unroll
    for (int s = 0; s < 8; s++) {
        float a1 = v1[s], a2 = v2[s];
        int   ai = i1[s];
        #pragma unroll
        for (int off = 1; off <= 8; off <<= 1) {
            float o1 = __shfl_xor_sync(0xffffffffu, a1, off);
            float o2 = __shfl_xor_sync(0xffffffffu, a2, off);
            int   oi = __shfl_xor_sync(0xffffffffu, ai, off);
            if (o1 > a1 || (o1 == a1 && oi < ai)) {
                a2 = fmaxf(a1, o2); a1 = o1; ai = oi;
            } else {
                a2 = fmaxf(a2, o1);
            }
        }
        if (tx == 0) {
            int row = (s < 4) ? (4 * ty + s) : (64 + 4 * ty + (s - 4));
            s_ind[row] = ai;
            s_flg[row] = (a1 - a2 <= TH_GAP) ? 1 : 0;
        }
    }
    __syncthreads();

    // fused segment sums: warp w handles 16 rows; lanes cover d and d+32
    #pragma unroll
    for (int t = 0; t < 16; t++) {
        int row = w * 16 + t;
        int k = s_ind[row];
        if (lane == 0) {
            g_ind[rb + row] = k;
            atomicAdd(&g_counts[k], 1);
            if (s_flg[row]) {
                int pos = atomicAdd(&g_nflag, 1);
                g_flag[pos] = rb + row;
            }
        }
        float xa = X[(size_t)(rb + row) * DIM + lane];
        float xb = X[(size_t)(rb + row) * DIM + 32 + lane];
        atomicAdd(&g_csum[k * 64 + lane],      xa);
        atomicAdd(&g_csum[k * 64 + 32 + lane], xb);
    }
}

// ---------------- exact fp32 recheck + correction -----------------------------
__global__ void __launch_bounds__(256)
recheck_kernel(const float* __restrict__ X) {
    __shared__ float fx[32 * 68];
    __shared__ float cz[64 * 68];
    const int tid  = threadIdx.x;
    const int w    = tid >> 5;
    const int lane = tid & 31;
    const int nf   = g_nflag;
    const float4* Ct4 = reinterpret_cast<const float4*>(g_Ct);

    for (int tile = blockIdx.x; tile * 32 < nf; tile += gridDim.x) {
        int base = tile * 32;
        int npts = nf - base; if (npts > 32) npts = 32;
        __syncthreads();
        for (int f = tid; f < npts * 16; f += 256) {
            int p = f >> 4, j = f & 15;
            int row = g_flag[base + p];
            *reinterpret_cast<float4*>(&fx[p * 68 + j * 4]) =
                *reinterpret_cast<const float4*>(X + (size_t)row * 64 + j * 4);
        }

        float bv[4];
        int   bk[4];
        #pragma unroll
        for (int ii = 0; ii < 4; ii++) { bv[ii] = -3.402823466e38f; bk[ii] = 0x7fffffff; }

        for (int ch = 0; ch < 16; ch++) {
            __syncthreads();
            #pragma unroll
            for (int i = 0; i < 4; i++) {
                int f = tid + i * 256;
                int n = f >> 4, j = f & 15;
                *reinterpret_cast<float4*>(&cz[n * 68 + j * 4]) = Ct4[(ch * 64 + n) * 16 + j];
            }
            __syncthreads();
            #pragma unroll
            for (int ii = 0; ii < 4; ii++) {
                int p = w * 4 + ii;
                if (p >= npts) continue;
                float s0 = 0.0f, s1 = 0.0f;
                #pragma unroll
                for (int d4 = 0; d4 < 16; d4++) {
                    float4 a  = *reinterpret_cast<const float4*>(&fx[p * 68 + d4 * 4]);
                    float4 b0 = *reinterpret_cast<const float4*>(&cz[lane * 68 + d4 * 4]);
                    float4 b1 = *reinterpret_cast<const float4*>(&cz[(lane + 32) * 68 + d4 * 4]);
                    s0 = fmaf(a.x, b0.x, s0); s0 = fmaf(a.y, b0.y, s0);
                    s0 = fmaf(a.z, b0.z, s0); s0 = fmaf(a.w, b0.w, s0);
                    s1 = fmaf(a.x, b1.x, s1); s1 = fmaf(a.y, b1.y, s1);
                    s1 = fmaf(a.z, b1.z, s1); s1 = fmaf(a.w, b1.w, s1);
                }
                int c0 = ch * 64 + lane;
                s0 = fmaf(2.0f, s0, -g_csq[c0]);
                s1 = fmaf(2.0f, s1, -g_csq[c0 + 32]);
                if (s0 > bv[ii]) { bv[ii] = s0; bk[ii] = c0; }
                if (s1 > bv[ii]) { bv[ii] = s1; bk[ii] = c0 + 32; }
            }
        }

        #pragma unroll
        for (int ii = 0; ii < 4; ii++) {
            int p = w * 4 + ii;
            float v = bv[ii];
            int   k = bk[ii];
            #pragma unroll
            for (int off = 16; off > 0; off >>= 1) {
                float ov = __shfl_xor_sync(0xffffffffu, v, off);
                int   ok = __shfl_xor_sync(0xffffffffu, k, off);
                if (ov > v || (ov == v && ok < k)) { v = ov; k = ok; }
            }
            if (p >= npts) continue;
            int row = g_flag[base + p];
            int oldk = g_ind[row];
            if (k != oldk) {
                if (lane == 0) {
                    g_ind[row] = k;
                    atomicAdd(&g_counts[oldk], -1);
                    atomicAdd(&g_counts[k], 1);
                }
                float xa = fx[p * 68 + lane];
                float xb = fx[p * 68 + 32 + lane];
                atomicAdd(&g_csum[oldk * 64 + lane], -xa);
                atomicAdd(&g_csum[k * 64 + lane],     xa);
                atomicAdd(&g_csum[oldk * 64 + 32 + lane], -xb);
                atomicAdd(&g_csum[k * 64 + 32 + lane],     xb);
            }
        }
    }
}

// ---------------- EMA update + normalize (parallel) ---------------------------
__global__ void update2_kernel(const float* __restrict__ cluster_size,
                               const float* __restrict__ cavg) {
    int i = blockIdx.x * blockDim.x + threadIdx.x;
    int k = i >> 6;
    int d = i & 63;
    float n = 0.99f * g_sum_cs + 0.01f * (float)N_PTS;
    float csz = 0.99f * cluster_size[k] + 0.01f * (float)g_counts[k];
    float cs = (csz + 1e-5f) / (n + (float)KCENT * 1e-5f) * n;
    float avg_new = 0.99f * cavg[d * KCENT + k] + 0.01f * g_csum[i];
    g_cnew[i] = avg_new / cs;
}

// ---------------- gather + loss -------------------------------------------------
__global__ void gather_kernel(const float* __restrict__ X, float* __restrict__ out) {
    float lsum = 0.0f;
    const int stride = gridDim.x * blockDim.x;
    const float4* Xv = reinterpret_cast<const float4*>(X);
    float4* Ov = reinterpret_cast<float4*>(out);
    for (int i = blockIdx.x * blockDim.x + threadIdx.x; i < N_PTS * DIM / 4; i += stride) {
        int n  = i >> 4;
        int d4 = (i & 15) * 4;
        float4 q = *reinterpret_cast<const float4*>(&g_cnew[g_ind[n] * 64 + d4]);
        float4 x = Xv[i];
        float4 o;
        o.x = x.x + (q.x - x.x);
        o.y = x.y + (q.y - x.y);
        o.z = x.z + (q.z - x.z);
        o.w = x.w + (q.w - x.w);
        Ov[i] = o;
        float dx = x.x - q.x, dy = x.y - q.y, dz = x.z - q.z, dw = x.w - q.w;
        lsum = fmaf(dx, dx, lsum);
        lsum = fmaf(dy, dy, lsum);
        lsum = fmaf(dz, dz, lsum);
        lsum = fmaf(dw, dw, lsum);
    }
    __shared__ float red[256];
    red[threadIdx.x] = lsum;
    __syncthreads();
    #pragma unroll
    for (int s = 128; s > 0; s >>= 1) {
        if (threadIdx.x < s) red[threadIdx.x] += red[threadIdx.x + s];
        __syncthreads();
    }
    if (threadIdx.x == 0) atomicAdd(&g_loss, red[0]);
}

__global__ void finalize_kernel(float* out, int out_size) {
    float loss = g_loss * (1.0f / 8388608.0f);   // 1/(N*D), exact
    for (int i = N_PTS * DIM; i < out_size; i++) out[i] = loss;
}

// -------------------------------------------------------------------------------
extern "C" void kernel_launch(void* const* d_in, const int* in_sizes, int n_in,
                              void* d_out, int out_size) {
    const float* x             = (const float*)d_in[0];  // [N, D]
    const float* centroids     = (const float*)d_in[1];  // [D, K]
    const float* cluster_size  = (const float*)d_in[2];  // [K]
    const float* centroids_avg = (const float*)d_in[3];  // [D, K]
    float* out = (float*)d_out;

    zero_kernel<<<(KCENT * DIM + 255) / 256, 256>>>();
    csq_kernel<<<KCENT / 256, 256>>>(centroids);
    sumcs_kernel<<<1, 1024>>>(cluster_size);
    prep_Ct<<<dim3(32, 2), 256>>>(centroids);
    prep_Xh<<<ASSIGN_BLOCKS, 256>>>(x);
    prep_Bh<<<(CHUNKS * 64 * 64 + 255) / 256, 256>>>(centroids);
    assign_kernel<<<ASSIGN_BLOCKS, 256>>>(x);
    recheck_kernel<<<256, 256>>>(x);
    update2_kernel<<<KCENT * DIM / 256, 256>>>(cluster_size, centroids_avg);
    gather_kernel<<<2048, 256>>>(x, out);
    finalize_kernel<<<1, 1>>>(out, out_size);
}

// round 8
// speedup vs baseline: 1.0727x; 1.0727x over previous
#include <cuda_runtime.h>
#include <cstdint>

#define N_PTS 131072
#define DIM   64
#define KCENT 1024

#define ROWS_BLK 128
#define ASSIGN_BLOCKS (N_PTS / ROWS_BLK)   // 1024
#define NCHK 8                              // K chunks of 128 cols
#define CH_F (65 * 132)                     // floats per chunk image (65 dims x 132 pad)
#define TH_ACC 0.01f                        // acc-units gap (score gap = 2x)

typedef unsigned long long u64;

// ---------------- device scratch (no allocation allowed) --------------------
__device__ float g_csq[KCENT];
__device__ int   g_ind[N_PTS];
__device__ int   g_counts[KCENT];
__device__ float g_csum[KCENT * DIM];
__device__ float g_cnew[KCENT * DIM];
__device__ float g_loss;
__device__ float g_sum_cs;
__device__ int   g_nflag;
__device__ int   g_flag[N_PTS];
__device__ float g_Ct[KCENT * DIM];              // C^T for recheck
__device__ __align__(16) float gBp[NCHK * CH_F]; // B chunk images (65 rows: C dims + -csq/2)

// ---------------- packed f32x2 helpers ----------------------------------------
__device__ __forceinline__ u64 ffma2(u64 a, u64 b, u64 c) {
    u64 d;
    asm("fma.rn.f32x2 %0, %1, %2, %3;" : "=l"(d) : "l"(a), "l"(b), "l"(c));
    return d;
}
__device__ __forceinline__ u64 bcast2(float v) {
    u64 d; asm("mov.b64 %0, {%1, %1};" : "=l"(d) : "f"(v)); return d;
}
__device__ __forceinline__ void unpack2(u64 v, float& lo, float& hi) {
    asm("mov.b64 {%0, %1}, %2;" : "=f"(lo), "=f"(hi) : "l"(v));
}
__device__ __forceinline__ uint32_t smem_u32(const void* p) {
    uint32_t a;
    asm("{ .reg .u64 t; cvta.to.shared.u64 t, %1; cvt.u32.u64 %0, t; }"
        : "=r"(a) : "l"(p));
    return a;
}

// ---------------- small kernels -----------------------------------------------
__global__ void zero_kernel() {
    int i = blockIdx.x * blockDim.x + threadIdx.x;
    if (i < KCENT * DIM) g_csum[i] = 0.0f;
    if (i < KCENT)       g_counts[i] = 0;
    if (i == 0)          { g_loss = 0.0f; g_nflag = 0; }
}

__global__ void csq_kernel(const float* __restrict__ C) {
    int k = blockIdx.x * blockDim.x + threadIdx.x;
    if (k < KCENT) {
        float s = 0.0f;
        #pragma unroll
        for (int d = 0; d < DIM; d++) {
            float c = C[d * KCENT + k];
            s = fmaf(c, c, s);
        }
        g_csq[k] = s;
    }
}

__global__ void sumcs_kernel(const float* __restrict__ cluster_size) {
    __shared__ float red[1024];
    int k = threadIdx.x;
    red[k] = cluster_size[k];
    __syncthreads();
    #pragma unroll
    for (int s = 512; s > 0; s >>= 1) {
        if (k < s) red[k] += red[k + s];
        __syncthreads();
    }
    if (k == 0) g_sum_cs = red[0];
}

// transpose C [64][1024] -> Ct [1024][64] (for exact recheck)
__global__ void prep_Ct(const float* __restrict__ C) {
    __shared__ float t[32][33];
    int tx = threadIdx.x & 31;
    int ty0 = threadIdx.x >> 5;
    int kb = blockIdx.x * 32;
    int db = blockIdx.y * 32;
    #pragma unroll
    for (int yy = 0; yy < 4; yy++) {
        int ty = ty0 + yy * 8;
        t[ty][tx] = C[(db + ty) * KCENT + kb + tx];
    }
    __syncthreads();
    #pragma unroll
    for (int yy = 0; yy < 4; yy++) {
        int ty = ty0 + yy * 8;
        g_Ct[(kb + ty) * DIM + db + tx] = t[tx][ty];
    }
}

// Build B chunk images: row d<64 = C[d][cc*128+col], row 64 = -csq/2
__global__ void prep_Bimg(const float* __restrict__ C) {
    int i = blockIdx.x * blockDim.x + threadIdx.x;
    if (i >= NCHK * 65 * 128) return;
    int col = i & 127;
    int d   = (i >> 7) % 65;
    int cc  = i / (65 * 128);
    float v = (d < 64) ? C[d * KCENT + cc * 128 + col]
                       : -0.5f * g_csq[cc * 128 + col];
    gBp[cc * CH_F + d * 132 + col] = v;
}

// ---------------- assign: FFMA2 GEMM, cp.async double-buffer, fused segsum ---
__device__ __forceinline__ void issue_chunk(uint32_t smem_dst, const float* gsrc, int tid) {
    #pragma unroll
    for (int j = 0; j < 9; j++) {
        int f = tid + j * 256;
        if (f < CH_F / 4)
            asm volatile("cp.async.cg.shared.global [%0], [%1], 16;"
                         :: "r"(smem_dst + f * 16), "l"(gsrc + f * 4));
    }
}

__global__ void __launch_bounds__(256, 2)
assign_kernel(const float* __restrict__ X) {
    extern __shared__ __align__(16) float sm[];
    float* xs  = sm;                       // [65][132]
    float* ch0 = sm + CH_F;
    float* ch1 = sm + 2 * CH_F;
    int* s_ind = (int*)(sm + 3 * CH_F);    // [128]
    int* s_flg = s_ind + 128;              // [128]

    const int tid  = threadIdx.x;
    const int tx   = tid & 15;
    const int ty   = tid >> 4;
    const int w    = tid >> 5;
    const int lane = tid & 31;
    const int rb   = blockIdx.x * ROWS_BLK;

    const uint32_t ch0a = smem_u32(ch0);
    const uint32_t ch1a = smem_u32(ch1);

    // prologue: async-load chunk 0
    issue_chunk(ch0a, gBp, tid);
    asm volatile("cp.async.commit_group;");

    // load X tile [128 x 64] transposed into xs (+ row 64 = 1.0)
    const float4* Xv = reinterpret_cast<const float4*>(X + (size_t)rb * DIM);
    #pragma unroll
    for (int j = 0; j < 8; j++) {
        int f = tid + j * 256;
        float4 v = Xv[f];
        int r = f >> 4;
        int d = (f & 15) * 4;
        xs[(d + 0) * 132 + r] = v.x;
        xs[(d + 1) * 132 + r] = v.y;
        xs[(d + 2) * 132 + r] = v.z;
        xs[(d + 3) * 132 + r] = v.w;
    }
    if (tid < 128) xs[64 * 132 + tid] = 1.0f;

    float v1[8], v2[8];
    int   i1[8];
    #pragma unroll
    for (int s = 0; s < 8; s++) { v1[s] = -3.402823466e38f; v2[s] = -3.402823466e38f; i1[s] = 0; }

    for (int cc = 0; cc < NCHK; cc++) {
        if (cc < NCHK - 1) {
            issue_chunk((cc & 1) ? ch0a : ch1a, gBp + (cc + 1) * CH_F, tid);
            asm volatile("cp.async.commit_group;");
            asm volatile("cp.async.wait_group 1;");
        } else {
            asm volatile("cp.async.wait_group 0;");
        }
        __syncthreads();

        const float* buf = (cc & 1) ? ch1 : ch0;
        // row stride: 132 floats = 33 ulonglong2; upper half (cols 64+) = +16
        const ulonglong2* bp = reinterpret_cast<const ulonglong2*>(buf) + tx;

        u64 acc[8][4];
        #pragma unroll
        for (int i = 0; i < 8; i++)
            #pragma unroll
            for (int jj = 0; jj < 4; jj++) acc[i][jj] = 0ULL;

        #pragma unroll 5
        for (int d = 0; d < 65; d++) {
            float4 a0 = *reinterpret_cast<const float4*>(&xs[d * 132 + 4 * ty]);
            float4 a1 = *reinterpret_cast<const float4*>(&xs[d * 132 + 64 + 4 * ty]);
            ulonglong2 b01 = bp[d * 33];        // cols 4tx .. 4tx+3
            ulonglong2 b23 = bp[d * 33 + 16];   // cols 64+4tx .. 64+4tx+3
            float a[8] = {a0.x, a0.y, a0.z, a0.w, a1.x, a1.y, a1.z, a1.w};
            #pragma unroll
            for (int i = 0; i < 8; i++) {
                u64 ad = bcast2(a[i]);
                acc[i][0] = ffma2(ad, b01.x, acc[i][0]);
                acc[i][1] = ffma2(ad, b01.y, acc[i][1]);
                acc[i][2] = ffma2(ad, b23.x, acc[i][2]);
                acc[i][3] = ffma2(ad, b23.y, acc[i][3]);
            }
        }

        // epilogue: raw-acc argmax top-2 (score = 2*acc - monotonic; csq folded)
        #pragma unroll
        for (int jj = 0; jj < 4; jj++) {
            int c0 = cc * 128 + ((jj < 2) ? (4 * tx + 2 * jj) : (64 + 4 * tx + 2 * (jj - 2)));
            #pragma unroll
            for (int i = 0; i < 8; i++) {
                float lo, hi;
                unpack2(acc[i][jj], lo, hi);
                if (lo > v1[i]) { v2[i] = v1[i]; v1[i] = lo; i1[i] = c0; }
                else if (lo > v2[i]) v2[i] = lo;
                if (hi > v1[i]) { v2[i] = v1[i]; v1[i] = hi; i1[i] = c0 + 1; }
                else if (hi > v2[i]) v2[i] = hi;
            }
        }
        __syncthreads();   // done reading buf before it is refilled
    }

    // reduce top-2 across the 16 tx-lanes sharing each row
    #pragma unroll
    for (int s = 0; s < 8; s++) {
        float a1v = v1[s], a2v = v2[s];
        int   ai = i1[s];
        #pragma unroll
        for (int off = 8; off > 0; off >>= 1) {
            float o1 = __shfl_xor_sync(0xffffffffu, a1v, off);
            float o2 = __shfl_xor_sync(0xffffffffu, a2v, off);
            int   oi = __shfl_xor_sync(0xffffffffu, ai, off);
            if (o1 > a1v || (o1 == a1v && oi < ai)) {
                a2v = fmaxf(a1v, o2); a1v = o1; ai = oi;
            } else {
                a2v = fmaxf(a2v, o1);
            }
        }
        if (tx == 0) {
            int row = (s < 4) ? (4 * ty + s) : (64 + 4 * ty + (s - 4));
            s_ind[row] = ai;
            s_flg[row] = (a1v - a2v <= TH_ACC) ? 1 : 0;
        }
    }
    __syncthreads();

    // fused segment sums: warp w handles 16 rows; lanes cover d and d+32
    #pragma unroll
    for (int t = 0; t < 16; t++) {
        int row = w * 16 + t;
        int k = s_ind[row];
        if (lane == 0) {
            g_ind[rb + row] = k;
            atomicAdd(&g_counts[k], 1);
            if (s_flg[row]) {
                int pos = atomicAdd(&g_nflag, 1);
                g_flag[pos] = rb + row;
            }
        }
        atomicAdd(&g_csum[k * 64 + lane],      xs[lane * 132 + row]);
        atomicAdd(&g_csum[k * 64 + 32 + lane], xs[(32 + lane) * 132 + row]);
    }
}

// ---------------- exact fp32 recheck + correction -----------------------------
__global__ void __launch_bounds__(256)
recheck_kernel(const float* __restrict__ X) {
    __shared__ float fx[32 * 68];
    __shared__ float cz[64 * 68];
    const int tid  = threadIdx.x;
    const int w    = tid >> 5;
    const int lane = tid & 31;
    const int nf   = g_nflag;
    const float4* Ct4 = reinterpret_cast<const float4*>(g_Ct);

    for (int tile = blockIdx.x; tile * 32 < nf; tile += gridDim.x) {
        int base = tile * 32;
        int npts = nf - base; if (npts > 32) npts = 32;
        __syncthreads();
        for (int f = tid; f < npts * 16; f += 256) {
            int p = f >> 4, j = f & 15;
            int row = g_flag[base + p];
            *reinterpret_cast<float4*>(&fx[p * 68 + j * 4]) =
                *reinterpret_cast<const float4*>(X + (size_t)row * 64 + j * 4);
        }

        float bv[4];
        int   bk[4];
        #pragma unroll
        for (int ii = 0; ii < 4; ii++) { bv[ii] = -3.402823466e38f; bk[ii] = 0x7fffffff; }

        for (int ch = 0; ch < 16; ch++) {
            __syncthreads();
            #pragma unroll
            for (int i = 0; i < 4; i++) {
                int f = tid + i * 256;
                int n = f >> 4, j = f & 15;
                *reinterpret_cast<float4*>(&cz[n * 68 + j * 4]) = Ct4[(ch * 64 + n) * 16 + j];
            }
            __syncthreads();
            #pragma unroll
            for (int ii = 0; ii < 4; ii++) {
                int p = w * 4 + ii;
                if (p >= npts) continue;
                float s0 = 0.0f, s1 = 0.0f;
                #pragma unroll
                for (int d4 = 0; d4 < 16; d4++) {
                    float4 a  = *reinterpret_cast<const float4*>(&fx[p * 68 + d4 * 4]);
                    float4 b0 = *reinterpret_cast<const float4*>(&cz[lane * 68 + d4 * 4]);
                    float4 b1 = *reinterpret_cast<const float4*>(&cz[(lane + 32) * 68 + d4 * 4]);
                    s0 = fmaf(a.x, b0.x, s0); s0 = fmaf(a.y, b0.y, s0);
                    s0 = fmaf(a.z, b0.z, s0); s0 = fmaf(a.w, b0.w, s0);
                    s1 = fmaf(a.x, b1.x, s1); s1 = fmaf(a.y, b1.y, s1);
                    s1 = fmaf(a.z, b1.z, s1); s1 = fmaf(a.w, b1.w, s1);
                }
                int c0 = ch * 64 + lane;
                s0 = fmaf(2.0f, s0, -g_csq[c0]);
                s1 = fmaf(2.0f, s1, -g_csq[c0 + 32]);
                if (s0 > bv[ii]) { bv[ii] = s0; bk[ii] = c0; }
                if (s1 > bv[ii]) { bv[ii] = s1; bk[ii] = c0 + 32; }
            }
        }

        #pragma unroll
        for (int ii = 0; ii < 4; ii++) {
            int p = w * 4 + ii;
            float v = bv[ii];
            int   k = bk[ii];
            #pragma unroll
            for (int off = 16; off > 0; off >>= 1) {
                float ov = __shfl_xor_sync(0xffffffffu, v, off);
                int   ok = __shfl_xor_sync(0xffffffffu, k, off);
                if (ov > v || (ov == v && ok < k)) { v = ov; k = ok; }
            }
            if (p >= npts) continue;
            int row = g_flag[base + p];
            int oldk = g_ind[row];
            if (k != oldk) {
                if (lane == 0) {
                    g_ind[row] = k;
                    atomicAdd(&g_counts[oldk], -1);
                    atomicAdd(&g_counts[k], 1);
                }
                float xa = fx[p * 68 + lane];
                float xb = fx[p * 68 + 32 + lane];
                atomicAdd(&g_csum[oldk * 64 + lane], -xa);
                atomicAdd(&g_csum[k * 64 + lane],     xa);
                atomicAdd(&g_csum[oldk * 64 + 32 + lane], -xb);
                atomicAdd(&g_csum[k * 64 + 32 + lane],     xb);
            }
        }
    }
}

// ---------------- EMA update + normalize (parallel) ---------------------------
__global__ void update2_kernel(const float* __restrict__ cluster_size,
                               const float* __restrict__ cavg) {
    int i = blockIdx.x * blockDim.x + threadIdx.x;
    int k = i >> 6;
    int d = i & 63;
    float n = 0.99f * g_sum_cs + 0.01f * (float)N_PTS;
    float csz = 0.99f * cluster_size[k] + 0.01f * (float)g_counts[k];
    float cs = (csz + 1e-5f) / (n + (float)KCENT * 1e-5f) * n;
    float avg_new = 0.99f * cavg[d * KCENT + k] + 0.01f * g_csum[i];
    g_cnew[i] = avg_new / cs;
}

// ---------------- gather + loss -------------------------------------------------
__global__ void gather_kernel(const float* __restrict__ X, float* __restrict__ out) {
    float lsum = 0.0f;
    const int stride = gridDim.x * blockDim.x;
    const float4* Xv = reinterpret_cast<const float4*>(X);
    float4* Ov = reinterpret_cast<float4*>(out);
    for (int i = blockIdx.x * blockDim.x + threadIdx.x; i < N_PTS * DIM / 4; i += stride) {
        int n  = i >> 4;
        int d4 = (i & 15) * 4;
        float4 q = *reinterpret_cast<const float4*>(&g_cnew[g_ind[n] * 64 + d4]);
        float4 x = Xv[i];
        float4 o;
        o.x = x.x + (q.x - x.x);
        o.y = x.y + (q.y - x.y);
        o.z = x.z + (q.z - x.z);
        o.w = x.w + (q.w - x.w);
        Ov[i] = o;
        float dx = x.x - q.x, dy = x.y - q.y, dz = x.z - q.z, dw = x.w - q.w;
        lsum = fmaf(dx, dx, lsum);
        lsum = fmaf(dy, dy, lsum);
        lsum = fmaf(dz, dz, lsum);
        lsum = fmaf(dw, dw, lsum);
    }
    __shared__ float red[256];
    red[threadIdx.x] = lsum;
    __syncthreads();
    #pragma unroll
    for (int s = 128; s > 0; s >>= 1) {
        if (threadIdx.x < s) red[threadIdx.x] += red[threadIdx.x + s];
        __syncthreads();
    }
    if (threadIdx.x == 0) atomicAdd(&g_loss, red[0]);
}

__global__ void finalize_kernel(float* out, int out_size) {
    float loss = g_loss * (1.0f / 8388608.0f);   // 1/(N*D), exact
    for (int i = N_PTS * DIM; i < out_size; i++) out[i] = loss;
}

// -------------------------------------------------------------------------------
extern "C" void kernel_launch(void* const* d_in, const int* in_sizes, int n_in,
                              void* d_out, int out_size) {
    const float* x             = (const float*)d_in[0];  // [N, D]
    const float* centroids     = (const float*)d_in[1];  // [D, K]
    const float* cluster_size  = (const float*)d_in[2];  // [K]
    const float* centroids_avg = (const float*)d_in[3];  // [D, K]
    float* out = (float*)d_out;

    const int smem_bytes = (3 * CH_F + 256) * (int)sizeof(float);   // 103984
    cudaFuncSetAttribute(assign_kernel,
                         cudaFuncAttributeMaxDynamicSharedMemorySize, smem_bytes);

    zero_kernel<<<(KCENT * DIM + 255) / 256, 256>>>();
    csq_kernel<<<KCENT / 256, 256>>>(centroids);
    sumcs_kernel<<<1, 1024>>>(cluster_size);
    prep_Ct<<<dim3(32, 2), 256>>>(centroids);
    prep_Bimg<<<(NCHK * 65 * 128 + 255) / 256, 256>>>(centroids);
    assign_kernel<<<ASSIGN_BLOCKS, 256, smem_bytes>>>(x);
    recheck_kernel<<<256, 256>>>(x);
    update2_kernel<<<KCENT * DIM / 256, 256>>>(cluster_size, centroids_avg);
    gather_kernel<<<2048, 256>>>(x, out);
    finalize_kernel<<<1, 1>>>(out, out_size);
}